// round 12
// baseline (speedup 1.0000x reference)
#include <cuda_runtime.h>
#include <cuda_fp16.h>
#include <cstdint>

#define BSZ 1024
#define S 62
#define DIM 65
#define H 10
#define NT 512

#define W_FNH 0
#define W_FNL 2304
#define W_FRH 4608
#define W_FRL 6912
#define W_TNH 9216
#define W_TNL 11808
#define W_TRH 14400
#define W_TRL 16992
#define W_WH  19584
#define W_WL  24768
#define W_QH  29952
#define W_QL  32256
#define W_KH  34560
#define W_KL  36864
#define W_A1H 39168
#define W_A1L 41472
#define W_A2H 43776
#define W_A2L 46080
#define W_SS  48384
#define W_BIA 52992
#define W_G   55872
#define W_WRP 56016
#define W_FLG 56176
#define SMEM_WORDS 56180

__device__ uint32_t g_wh[40 * 72 * 36];
__device__ uint32_t g_wl[40 * 72 * 36];
__device__ float    g_gate[BSZ * DIM];
__device__ float    g_norms[BSZ * H];
__device__ int      g_ctr;

__device__ __forceinline__ void cp16(uint32_t dst, const void* src) {
    asm volatile("cp.async.cg.shared.global [%0], [%1], 16;\n" :: "r"(dst), "l"(src));
}
__device__ __forceinline__ void cp_commit() { asm volatile("cp.async.commit_group;\n"); }
__device__ __forceinline__ void cp_wait0()  { asm volatile("cp.async.wait_group 0;\n"); }

__device__ __forceinline__ void pack_hl(float x, float y, uint32_t& hw, uint32_t& lw) {
    const __half hx = __float2half_rn(x), hy = __float2half_rn(y);
    __half2 h = __halves2half2(hx, hy);
    __half2 l = __halves2half2(__float2half_rn(x - __half2float(hx)),
                               __float2half_rn(y - __half2float(hy)));
    hw = *reinterpret_cast<uint32_t*>(&h);
    lw = *reinterpret_cast<uint32_t*>(&l);
}
__device__ __forceinline__ void mma16(float* c, uint32_t a0, uint32_t a1,
                                      uint32_t a2, uint32_t a3, uint32_t b0, uint32_t b1) {
    asm volatile("mma.sync.aligned.m16n8k16.row.col.f32.f16.f16.f32 "
                 "{%0,%1,%2,%3}, {%4,%5,%6,%7}, {%8,%9}, {%0,%1,%2,%3};\n"
                 : "+f"(c[0]), "+f"(c[1]), "+f"(c[2]), "+f"(c[3])
                 : "r"(a0), "r"(a1), "r"(a2), "r"(a3), "r"(b0), "r"(b1));
}
__device__ __forceinline__ void mma8h(float* c, uint32_t a0, uint32_t a1, uint32_t b0) {
    asm volatile("mma.sync.aligned.m16n8k8.row.col.f32.f16.f16.f32 "
                 "{%0,%1,%2,%3}, {%4,%5}, {%6}, {%0,%1,%2,%3};\n"
                 : "+f"(c[0]), "+f"(c[1]), "+f"(c[2]), "+f"(c[3])
                 : "r"(a0), "r"(a1), "r"(b0));
}
__device__ __forceinline__ void ldsm4(uint32_t& r0, uint32_t& r1, uint32_t& r2,
                                      uint32_t& r3, uint32_t a) {
    asm volatile("ldmatrix.sync.aligned.m8n8.x4.shared.b16 {%0,%1,%2,%3}, [%4];\n"
                 : "=r"(r0), "=r"(r1), "=r"(r2), "=r"(r3) : "r"(a));
}
__device__ __forceinline__ void ldsm2(uint32_t& r0, uint32_t& r1, uint32_t a) {
    asm volatile("ldmatrix.sync.aligned.m8n8.x2.shared.b16 {%0,%1}, [%2];\n"
                 : "=r"(r0), "=r"(r1) : "r"(a));
}
__device__ __forceinline__ uint32_t s2u(const void* p) {
    return (uint32_t)__cvta_generic_to_shared(p);
}

__global__ void prep_kernel(const float* __restrict__ Fn, const float* __restrict__ Fr,
                            const float* __restrict__ Wg, const float* __restrict__ bg,
                            const float* __restrict__ Wq1, const float* __restrict__ Wk1,
                            const float* __restrict__ Wq2, const float* __restrict__ Wk2) {
    const int t = threadIdx.x;
    if (blockIdx.x < BSZ) {
        __shared__ float mean[132];
        const int b = blockIdx.x;
        if (t < 2 * DIM) {
            const float* src = (t < DIM) ? (Fn + (size_t)b * S * DIM + t)
                                         : (Fr + (size_t)b * S * DIM + t - DIM);
            float s = 0.f;
            for (int i = 0; i < S; i++) s += src[i * DIM];
            mean[t] = s * (1.0f / (float)S);
        }
        __syncthreads();
        if (t < DIM) {
            float acc = bg[t];
            const float* wr = Wg + t * 2 * DIM;
#pragma unroll 10
            for (int c = 0; c < 2 * DIM; c++) acc = fmaf(wr[c], mean[c], acc);
            g_gate[b * DIM + t] = 1.0f / (1.0f + __expf(-acc));
        }
    } else {
        const float* srcs[4] = { Wq1, Wk1, Wq2, Wk2 };
        const int total = 40 * 72 * 36;
        for (int idx = (blockIdx.x - BSZ) * 256 + t; idx < total; idx += 160 * 256) {
            const int m = idx / (72 * 36);
            const int rem = idx - m * 72 * 36;
            const int n = rem / 36, kw = rem - n * 36;
            const float* src = srcs[m & 3] + (m >> 2) * DIM * DIM;
            const int k0 = 2 * kw, k1 = k0 + 1;
            const float v0 = (n < DIM && k0 < DIM) ? src[n * DIM + k0] : 0.f;
            const float v1 = (n < DIM && k1 < DIM) ? src[n * DIM + k1] : 0.f;
            uint32_t hw, lw;
            pack_hl(v0, v1, hw, lw);
            g_wh[idx] = hw; g_wl[idx] = lw;
        }
    }
}

// Warp tile: A [m][kw], B [n][kw], stride 36 words, hi/lo planes, 3-term split.
// NS = n8-tiles per warp (1..5). EPI0 pack+bias -> Q planes; EPI1 scores*scale;
// EPI2 gmem gated; EPI3 loss sum.
template <int EPI, int NS, bool K8>
__device__ __forceinline__ float mma_tile(
    const uint32_t* __restrict__ AH, const uint32_t* __restrict__ AL,
    const uint32_t* __restrict__ BH, const uint32_t* __restrict__ BL,
    const int mt, const int n0, void* c0, void* c1,
    const float* __restrict__ aux, const float scale)
{
    const int lane = threadIdx.x & 31, lr = lane >> 2, lc = lane & 3;
    float acc[NS][4];
#pragma unroll
    for (int ns = 0; ns < NS; ns++)
        acc[ns][0] = acc[ns][1] = acc[ns][2] = acc[ns][3] = 0.f;

    const int ar = lane & 15, ac4 = (lane >> 4) << 2;
    const uint32_t aH = s2u(AH) + (((mt * 16 + ar) * 36 + ac4) << 2);
    const uint32_t aL = s2u(AL) + (((mt * 16 + ar) * 36 + ac4) << 2);
    const int br = (lane & 7) | ((lane >> 4) << 3), bc4 = ((lane >> 3) & 1) << 2;
    const uint32_t bHp = s2u(BH) + (((n0 + br) * 36 + bc4) << 2);
    const uint32_t bLp = s2u(BL) + (((n0 + br) * 36 + bc4) << 2);
    const int xr = n0 + (NS & ~1) * 8 + (lane & 7), xc4 = ((lane >> 3) & 1) << 2;
    const uint32_t bHx = s2u(BH) + ((xr * 36 + xc4) << 2);
    const uint32_t bLx = s2u(BL) + ((xr * 36 + xc4) << 2);

#pragma unroll
    for (int s = 0; s < 4; s++) {
        const uint32_t kb = 32u * s;
        uint32_t a0, a1, a2, a3, e0, e1, e2, e3;
        ldsm4(a0, a1, a2, a3, aH + kb);
        ldsm4(e0, e1, e2, e3, aL + kb);
#pragma unroll
        for (int p = 0; p < NS / 2; p++) {
            uint32_t b0, b1, b2, b3, f0, f1, f2, f3;
            ldsm4(b0, b1, b2, b3, bHp + 2304u * p + kb);
            ldsm4(f0, f1, f2, f3, bLp + 2304u * p + kb);
            mma16(acc[2 * p], a0, a1, a2, a3, b0, b1);
            mma16(acc[2 * p], e0, e1, e2, e3, b0, b1);
            mma16(acc[2 * p], a0, a1, a2, a3, f0, f1);
            mma16(acc[2 * p + 1], a0, a1, a2, a3, b2, b3);
            mma16(acc[2 * p + 1], e0, e1, e2, e3, b2, b3);
            mma16(acc[2 * p + 1], a0, a1, a2, a3, f2, f3);
        }
        if (NS & 1) {
            uint32_t x0, x1, y0, y1;
            ldsm2(x0, x1, bHx + kb);
            ldsm2(y0, y1, bLx + kb);
            mma16(acc[NS - 1], a0, a1, a2, a3, x0, x1);
            mma16(acc[NS - 1], e0, e1, e2, e3, x0, x1);
            mma16(acc[NS - 1], a0, a1, a2, a3, y0, y1);
        }
    }
    if (K8) {
        const uint32_t* ah = AH + (mt * 16 + lr) * 36 + lc;
        const uint32_t* al = AL + (mt * 16 + lr) * 36 + lc;
        const uint32_t h0 = ah[32], h1 = ah[8 * 36 + 32];
        const uint32_t l0 = al[32], l1 = al[8 * 36 + 32];
#pragma unroll
        for (int ns = 0; ns < NS; ns++) {
            const int nb = n0 + ns * 8;
            const uint32_t p = BH[(nb + lr) * 36 + lc + 32];
            const uint32_t q = BL[(nb + lr) * 36 + lc + 32];
            mma8h(acc[ns], h0, h1, p);
            mma8h(acc[ns], l0, l1, p);
            mma8h(acc[ns], h0, h1, q);
        }
    }

    float ss = 0.f;
    const int r0 = mt * 16 + lr, rr = r0 + 8;
#pragma unroll
    for (int ns = 0; ns < NS; ns++) {
        const int col = n0 + ns * 8 + 2 * lc;
        if (EPI == 0) {
            uint32_t* cH = (uint32_t*)c0;
            uint32_t* cL = (uint32_t*)c1;
            const float b0v = aux[col], b1v = aux[col + 1];
            const int kw = (n0 >> 1) + 4 * ns + lc;
            uint32_t hw, lw;
            pack_hl(acc[ns][0] + b0v, acc[ns][1] + b1v, hw, lw);
            cH[r0 * 36 + kw] = hw; cL[r0 * 36 + kw] = lw;
            pack_hl(acc[ns][2] + b0v, acc[ns][3] + b1v, hw, lw);
            cH[rr * 36 + kw] = hw; cL[rr * 36 + kw] = lw;
        } else if (EPI == 1) {
            float* cS = (float*)c0;
            *(float2*)(cS + r0 * 72 + col) = make_float2(acc[ns][0] * scale, acc[ns][1] * scale);
            *(float2*)(cS + rr * 72 + col) = make_float2(acc[ns][2] * scale, acc[ns][3] * scale);
        } else if (EPI == 2) {
            float* o = (float*)c0;
            if (col < 64) {
                const float ga = aux[col], gb = aux[col + 1];
                o[r0 * DIM + col] = ga * acc[ns][0];
                o[r0 * DIM + col + 1] = gb * acc[ns][1];
                if (rr < S) {
                    o[rr * DIM + col] = ga * acc[ns][2];
                    o[rr * DIM + col + 1] = gb * acc[ns][3];
                }
            } else if (col == 64) {
                o[r0 * DIM + 64] = aux[64] * acc[ns][0];
                if (rr < S) o[rr * DIM + 64] = aux[64] * acc[ns][2];
            }
        } else {
            if (col < S) { const float d = acc[ns][0] - ((r0 == col) ? 1.f : 0.f); ss = fmaf(d, d, ss); }
            if (col + 1 < S) { const float d = acc[ns][1] - ((r0 == col + 1) ? 1.f : 0.f); ss = fmaf(d, d, ss); }
            if (rr < S) {
                if (col < S) { const float d = acc[ns][2] - ((rr == col) ? 1.f : 0.f); ss = fmaf(d, d, ss); }
                if (col + 1 < S) { const float d = acc[ns][3] - ((rr == col + 1) ? 1.f : 0.f); ss = fmaf(d, d, ss); }
            }
        }
    }
    return ss;
}

// 8-warp GEMM over N=72: gp=0 -> cols 0..31 (NS=4), gp=1 -> cols 32..71 (NS=5)
template <int EPI, bool K8>
__device__ __forceinline__ float half_gemm(
    const uint32_t* AH, const uint32_t* AL, const uint32_t* BH, const uint32_t* BL,
    int mt, int gp, void* c0, void* c1, const float* aux)
{
    if (gp == 0) return mma_tile<EPI, 4, K8>(AH, AL, BH, BL, mt, 0, c0, c1, aux, 0.f);
    return mma_tile<EPI, 5, K8>(AH, AL, BH, BL, mt, 32, c0, c1, aux, 0.f);
}

__device__ __forceinline__ void softmax_pack(const float* __restrict__ sS,
                                             uint32_t* __restrict__ AHp,
                                             uint32_t* __restrict__ ALp) {
    const int w = threadIdx.x >> 5, lane = threadIdx.x & 31;
    const bool ok1 = (lane + 32) < S;
    for (int r = w; r < S; r += 16) {
        const float* row = sS + r * 72;
        const float v0 = row[lane];
        const float v1 = ok1 ? row[lane + 32] : -1e30f;
        float m = fmaxf(v0, v1);
#pragma unroll
        for (int off = 16; off; off >>= 1) m = fmaxf(m, __shfl_xor_sync(0xffffffffu, m, off));
        const float e0 = __expf(v0 - m);
        const float e1 = ok1 ? __expf(v1 - m) : 0.f;
        float s = e0 + e1;
#pragma unroll
        for (int off = 16; off; off >>= 1) s += __shfl_xor_sync(0xffffffffu, s, off);
        const float inv = 1.0f / s;
        const float p0 = e0 * inv, p1 = ok1 ? e1 * inv : 0.f;
        const float p0n = __shfl_down_sync(0xffffffffu, p0, 1);
        const float p1n = __shfl_down_sync(0xffffffffu, p1, 1);
        if ((lane & 1) == 0) {
            uint32_t hw, lw;
            pack_hl(p0, p0n, hw, lw);
            AHp[r * 36 + (lane >> 1)] = hw; ALp[r * 36 + (lane >> 1)] = lw;
            pack_hl(p1, p1n, hw, lw);
            AHp[r * 36 + (lane >> 1) + 16] = hw; ALp[r * 36 + (lane >> 1) + 16] = lw;
        }
    }
}

__device__ __forceinline__ void prefetch_wdir(int h, int d, uint32_t* sWH, uint32_t* sWL) {
    const int base = (h * 4 + 2 * d) * 2592;
    const float4* sh = (const float4*)(g_wh + base);
    const float4* sl = (const float4*)(g_wl + base);
    const uint32_t dh = s2u(sWH), dl = s2u(sWL);
    for (int j = threadIdx.x; j < 1296; j += NT) {
        cp16(dh + 16u * j, sh + j);
        cp16(dl + 16u * j, sl + j);
    }
    cp_commit();
}

__global__ void __launch_bounds__(NT, 1)
fused_kernel(const float* __restrict__ Fn, const float* __restrict__ Fr,
             const float* __restrict__ bq1, const float* __restrict__ bk1,
             const float* __restrict__ bq2, const float* __restrict__ bk2,
             float* __restrict__ out, float* __restrict__ out_loss)
{
    extern __shared__ uint32_t sm[];
    const int tid = threadIdx.x, b = blockIdx.x, w = tid >> 5;
    const int half = w >> 3, mt4 = w & 3, gp = (w >> 2) & 1, qg = w >> 2;
    float* sS = (float*)(sm + W_SS);
    float* sBias = (float*)(sm + W_BIA);
    float* sG = (float*)(sm + W_G);
    float* swarp = (float*)(sm + W_WRP);
    int* sflag = (int*)(sm + W_FLG);

    {
        float4* z = (float4*)sm;
        const float4 z4 = make_float4(0.f, 0.f, 0.f, 0.f);
        for (int i = tid; i < SMEM_WORDS / 4; i += NT) z[i] = z4;
    }
    __syncthreads();
    prefetch_wdir(0, 0, sm + W_WH, sm + W_WL);

    const float* fn = Fn + (size_t)b * S * DIM;
    const float* fr = Fr + (size_t)b * S * DIM;
    for (int idx = tid; idx < S * 33; idx += NT) {
        const int r = idx / 33, kw = idx - r * 33;
        const int k0 = 2 * kw, k1 = k0 + 1;
        uint32_t hw, lw;
        pack_hl(fn[r * DIM + k0], (k1 < DIM) ? fn[r * DIM + k1] : 0.f, hw, lw);
        sm[W_FNH + r * 36 + kw] = hw; sm[W_FNL + r * 36 + kw] = lw;
        pack_hl(fr[r * DIM + k0], (k1 < DIM) ? fr[r * DIM + k1] : 0.f, hw, lw);
        sm[W_FRH + r * 36 + kw] = hw; sm[W_FRL + r * 36 + kw] = lw;
    }
    for (int idx = tid; idx < DIM * 31; idx += NT) {
        const int d = idx / 31, rw = idx - d * 31;
        const int r0i = 2 * rw, r1i = r0i + 1;
        uint32_t hw, lw;
        pack_hl(fn[r0i * DIM + d], fn[r1i * DIM + d], hw, lw);
        sm[W_TNH + d * 36 + rw] = hw; sm[W_TNL + d * 36 + rw] = lw;
        pack_hl(fr[r0i * DIM + d], fr[r1i * DIM + d], hw, lw);
        sm[W_TRH + d * 36 + rw] = hw; sm[W_TRL + d * 36 + rw] = lw;
    }
    {
        const float* bsrc[4] = { bq1, bk1, bq2, bk2 };
        for (int idx = tid; idx < 40 * DIM; idx += NT) {
            const int m = idx / DIM, o = idx - m * DIM;
            sBias[m * 72 + o] = bsrc[m & 3][(m >> 2) * DIM + o];
        }
    }
    if (tid < DIM) {
        const float gg = g_gate[b * DIM + tid];
        sG[tid] = gg; sG[72 + tid] = 1.0f - gg;
    }
    const float scale = rsqrtf((float)DIM);
    cp_wait0();
    __syncthreads();

    for (int h = 0; h < H; h++) {
        float* o1 = out + ((size_t)(b * H + h) * 124) * DIM;
        float* o2 = o1 + (size_t)S * DIM;

        // P1: dir1 dual projections
        if (half == 0)
            half_gemm<0, true>(sm + W_FNH, sm + W_FNL, sm + W_WH, sm + W_WL,
                               mt4, gp, sm + W_QH, sm + W_QL, sBias + (h * 4 + 0) * 72);
        else
            half_gemm<0, true>(sm + W_FRH, sm + W_FRL, sm + W_WH + 2592, sm + W_WL + 2592,
                               mt4, gp, sm + W_KH, sm + W_KL, sBias + (h * 4 + 1) * 72);
        __syncthreads();

        // P2: prefetch dir2; logits1; wait W
        prefetch_wdir(h, 1, sm + W_WH, sm + W_WL);
        mma_tile<1, 2, true>(sm + W_QH, sm + W_QL, sm + W_KH, sm + W_KL,
                             mt4, qg * 16, sS, 0, 0, scale);
        cp_wait0();
        __syncthreads();

        // P3: softmax1 + dir2 dual projections (disjoint buffers)
        softmax_pack(sS, sm + W_A1H, sm + W_A1L);
        if (half == 0)
            half_gemm<0, true>(sm + W_FRH, sm + W_FRL, sm + W_WH, sm + W_WL,
                               mt4, gp, sm + W_QH, sm + W_QL, sBias + (h * 4 + 2) * 72);
        else
            half_gemm<0, true>(sm + W_FNH, sm + W_FNL, sm + W_WH + 2592, sm + W_WL + 2592,
                               mt4, gp, sm + W_KH, sm + W_KL, sBias + (h * 4 + 3) * 72);
        __syncthreads();

        // P4: prefetch next dir1; logits2
        if (h + 1 < H) prefetch_wdir(h + 1, 0, sm + W_WH, sm + W_WL);
        mma_tile<1, 2, true>(sm + W_QH, sm + W_QL, sm + W_KH, sm + W_KL,
                             mt4, qg * 16, sS, 0, 0, scale);
        __syncthreads();

        // P5: softmax2
        softmax_pack(sS, sm + W_A2H, sm + W_A2L);
        __syncthreads();

        // P6: loss gram (16 warps) + dual gated outputs; wait next W
        float ss = mma_tile<3, 2, false>(sm + W_A1H, sm + W_A1L, sm + W_A2H, sm + W_A2L,
                                         mt4, qg * 16, 0, 0, 0, 0.f);
        if (half == 0)
            half_gemm<2, false>(sm + W_A1H, sm + W_A1L, sm + W_TRH, sm + W_TRL,
                                mt4, gp, o1, 0, sG);
        else
            half_gemm<2, false>(sm + W_A2H, sm + W_A2L, sm + W_TNH, sm + W_TNL,
                                mt4, gp, o2, 0, sG + 72);
#pragma unroll
        for (int off = 16; off; off >>= 1) ss += __shfl_xor_sync(0xffffffffu, ss, off);
        if ((tid & 31) == 0) swarp[h * 16 + w] = ss;
        cp_wait0();
        __syncthreads();
    }

    // deferred norms
    if (tid < H) {
        float t = 0.f;
#pragma unroll
        for (int ww = 0; ww < 16; ww++) t += swarp[tid * 16 + ww];
        g_norms[b * H + tid] = sqrtf(t);
    }
    __threadfence();
    __syncthreads();
    if (tid == 0) *sflag = ((atomicAdd(&g_ctr, 1) % BSZ) == BSZ - 1) ? 1 : 0;
    __syncthreads();
    if (*sflag) {
        float s = 0.f;
        for (int i = tid; i < BSZ * H; i += NT) s += g_norms[i];
#pragma unroll
        for (int off = 16; off; off >>= 1) s += __shfl_xor_sync(0xffffffffu, s, off);
        if ((tid & 31) == 0) swarp[w] = s;
        __syncthreads();
        if (tid == 0) {
            float t = 0.f;
#pragma unroll
            for (int ww = 0; ww < 16; ww++) t += swarp[ww];
            *out_loss = t / (float)(BSZ * H);
        }
    }
}

extern "C" void kernel_launch(void* const* d_in, const int* in_sizes, int n_in,
                              void* d_out, int out_size)
{
    const float* Fn  = (const float*)d_in[0];
    const float* Fr  = (const float*)d_in[1];
    const float* Wq1 = (const float*)d_in[2];
    const float* bq1 = (const float*)d_in[3];
    const float* Wk1 = (const float*)d_in[4];
    const float* bk1 = (const float*)d_in[5];
    const float* Wq2 = (const float*)d_in[6];
    const float* bq2 = (const float*)d_in[7];
    const float* Wk2 = (const float*)d_in[8];
    const float* bk2 = (const float*)d_in[9];
    const float* Wg  = (const float*)d_in[10];
    const float* bg  = (const float*)d_in[11];
    float* out = (float*)d_out;

    prep_kernel<<<BSZ + 160, 256>>>(Fn, Fr, Wg, bg, Wq1, Wk1, Wq2, Wk2);
    const int smem_bytes = SMEM_WORDS * 4;
    cudaFuncSetAttribute(fused_kernel, cudaFuncAttributeMaxDynamicSharedMemorySize, smem_bytes);
    fused_kernel<<<BSZ, NT, smem_bytes>>>(Fn, Fr, bq1, bk1, bq2, bk2,
                                          out, out + (size_t)out_size - 1);
}